// round 2
// baseline (speedup 1.0000x reference)
#include <cuda_runtime.h>

// DWT_2D Haar: x [16,64,256,256] f32 -> (LL,LH,HL,HH) each [16,64,128,128]
// Algebraic collapse of the 4-GEMM reference: each band pixel = +-sum of a
// disjoint 2x2 input block * 0.5. Pure streaming kernel; HBM-bound.
//
// R2 changes vs R1:
//  - __ldcs / __stcs streaming hints (no reuse; evict-first through L2)
//  - 8 output cols per thread (MLP 4 -> 8 front-batched LDG.128)

static constexpr int NIMG      = 16 * 64;          // 1024
static constexpr int IN_W      = 256;
static constexpr int OUT_W     = 128;
static constexpr int IN_IMG    = 256 * 256;        // 65536
static constexpr int OUT_IMG   = 128 * 128;        // 16384
static constexpr long long BAND_STRIDE = (long long)NIMG * OUT_IMG; // 16777216

__device__ __forceinline__ void haar4(const float4& p, const float4& q,
                                      float4& ll, float4& lh, float4& hl, float4& hh,
                                      int lane /*0 or 1: which half of outputs*/)
{
    // p = top row 4 floats (2 output cols), q = bottom row 4 floats
    float sab0 = p.x + p.y, dab0 = p.x - p.y;
    float scd0 = q.x + q.y, dcd0 = q.x - q.y;
    float sab1 = p.z + p.w, dab1 = p.z - p.w;
    float scd1 = q.z + q.w, dcd1 = q.z - q.w;
    if (lane == 0) {
        ll.x = 0.5f * (sab0 + scd0);  ll.y = 0.5f * (sab1 + scd1);
        lh.x = 0.5f * (dab0 + dcd0);  lh.y = 0.5f * (dab1 + dcd1);
        hl.x = 0.5f * (sab0 - scd0);  hl.y = 0.5f * (sab1 - scd1);
        hh.x = 0.5f * (dab0 - dcd0);  hh.y = 0.5f * (dab1 - dcd1);
    } else {
        ll.z = 0.5f * (sab0 + scd0);  ll.w = 0.5f * (sab1 + scd1);
        lh.z = 0.5f * (dab0 + dcd0);  lh.w = 0.5f * (dab1 + dcd1);
        hl.z = 0.5f * (sab0 - scd0);  hl.w = 0.5f * (sab1 - scd1);
        hh.z = 0.5f * (dab0 - dcd0);  hh.w = 0.5f * (dab1 - dcd1);
    }
}

__global__ __launch_bounds__(256)
void dwt2d_haar_kernel(const float* __restrict__ x, float* __restrict__ out)
{
    int t = blockIdx.x * blockDim.x + threadIdx.x;
    // t layout: [n (1024)] [i (128)] [j8 (16)] -> 2,097,152 threads
    int j8 = t & 15;          // group of 8 output cols
    int i  = (t >> 4) & 127;  // output row
    int n  = t >> 11;         // image index

    const float4* __restrict__ r0 =
        reinterpret_cast<const float4*>(x + (long long)n * IN_IMG + (long long)(2 * i)     * IN_W) + (j8 << 2);
    const float4* __restrict__ r1 =
        reinterpret_cast<const float4*>(x + (long long)n * IN_IMG + (long long)(2 * i + 1) * IN_W) + (j8 << 2);

    // Front-batched streaming loads: 8x LDG.128 (64 B top row + 64 B bottom row)
    float4 p0 = __ldcs(r0 + 0);
    float4 p1 = __ldcs(r0 + 1);
    float4 p2 = __ldcs(r0 + 2);
    float4 p3 = __ldcs(r0 + 3);
    float4 q0 = __ldcs(r1 + 0);
    float4 q1 = __ldcs(r1 + 1);
    float4 q2 = __ldcs(r1 + 2);
    float4 q3 = __ldcs(r1 + 3);

    float4 llA, lhA, hlA, hhA;   // output cols 0..3
    float4 llB, lhB, hlB, hhB;   // output cols 4..7
    haar4(p0, q0, llA, lhA, hlA, hhA, 0);
    haar4(p1, q1, llA, lhA, hlA, hhA, 1);
    haar4(p2, q2, llB, lhB, hlB, hhB, 0);
    haar4(p3, q3, llB, lhB, hlB, hhB, 1);

    long long obase4 = ((long long)n * OUT_IMG + (long long)i * OUT_W + (j8 << 3)) >> 2;
    float4* __restrict__ o4 = reinterpret_cast<float4*>(out) + obase4;
    const long long bs4 = BAND_STRIDE >> 2;   // band stride in float4 units

    __stcs(o4 + 0,           llA);  __stcs(o4 + 1,           llB);  // LL
    __stcs(o4 + bs4,         lhA);  __stcs(o4 + bs4 + 1,     lhB);  // LH
    __stcs(o4 + 2 * bs4,     hlA);  __stcs(o4 + 2 * bs4 + 1, hlB);  // HL
    __stcs(o4 + 3 * bs4,     hhA);  __stcs(o4 + 3 * bs4 + 1, hhB);  // HH
}

extern "C" void kernel_launch(void* const* d_in, const int* in_sizes, int n_in,
                              void* d_out, int out_size)
{
    const float* x = (const float*)d_in[0];   // [16,64,256,256] f32
    // d_in[1..4] are the Haar DWT matrices -- algebraically folded, unused.
    float* out = (float*)d_out;               // 4 x [16,64,128,128] f32 concat

    // total threads = 1024 * 128 * 16 = 2,097,152
    int threads = 256;
    int blocks  = (NIMG * 128 * 16) / threads;  // 8192
    dwt2d_haar_kernel<<<blocks, threads>>>(x, out);
}

// round 3
// speedup vs baseline: 1.1221x; 1.1221x over previous
#include <cuda_runtime.h>

// DWT_2D Haar: x [16,64,256,256] f32 -> (LL,LH,HL,HH) each [16,64,128,128]
// Algebraic collapse of the 4-GEMM reference: each band pixel = +-sum of a
// disjoint 2x2 input block * 0.5. Pure streaming kernel; HBM-bound.
//
// R3 = R1 structure (proven 81.8% DRAM) + ONE change: __stcs streaming stores.

static constexpr int NIMG      = 16 * 64;          // 1024
static constexpr int IN_W      = 256;
static constexpr int OUT_W     = 128;
static constexpr int IN_IMG    = 256 * 256;        // 65536
static constexpr int OUT_IMG   = 128 * 128;        // 16384
static constexpr long long BAND_STRIDE = (long long)NIMG * OUT_IMG; // 16777216

__global__ __launch_bounds__(256)
void dwt2d_haar_kernel(const float* __restrict__ x, float* __restrict__ out)
{
    int t = blockIdx.x * blockDim.x + threadIdx.x;
    // t layout: [n (1024)] [i (128)] [j4 (32)]   -> 4,194,304 threads total
    int j4 = t & 31;          // output col group (4 cols each)
    int i  = (t >> 5) & 127;  // output row
    int n  = t >> 12;         // image index

    const float4* __restrict__ r0 =
        reinterpret_cast<const float4*>(x + (long long)n * IN_IMG + (long long)(2 * i)     * IN_W) + (j4 << 1);
    const float4* __restrict__ r1 =
        reinterpret_cast<const float4*>(x + (long long)n * IN_IMG + (long long)(2 * i + 1) * IN_W) + (j4 << 1);

    // 8 input cols -> 4 output cols (4x LDG.128, plain cached loads as in R1)
    float4 p0 = r0[0];
    float4 p1 = r0[1];
    float4 q0 = r1[0];
    float4 q1 = r1[1];

    float4 ll, lh, hl, hh;
    {
        float a = p0.x, b = p0.y, c = q0.x, d = q0.y;
        ll.x = 0.5f * ((a + b) + (c + d));
        lh.x = 0.5f * ((a - b) + (c - d));
        hl.x = 0.5f * ((a + b) - (c + d));
        hh.x = 0.5f * ((a - b) - (c - d));
    }
    {
        float a = p0.z, b = p0.w, c = q0.z, d = q0.w;
        ll.y = 0.5f * ((a + b) + (c + d));
        lh.y = 0.5f * ((a - b) + (c - d));
        hl.y = 0.5f * ((a + b) - (c + d));
        hh.y = 0.5f * ((a - b) - (c - d));
    }
    {
        float a = p1.x, b = p1.y, c = q1.x, d = q1.y;
        ll.z = 0.5f * ((a + b) + (c + d));
        lh.z = 0.5f * ((a - b) + (c - d));
        hl.z = 0.5f * ((a + b) - (c + d));
        hh.z = 0.5f * ((a - b) - (c - d));
    }
    {
        float a = p1.z, b = p1.w, c = q1.z, d = q1.w;
        ll.w = 0.5f * ((a + b) + (c + d));
        lh.w = 0.5f * ((a - b) + (c - d));
        hl.w = 0.5f * ((a + b) - (c + d));
        hh.w = 0.5f * ((a - b) - (c - d));
    }

    long long obase = (long long)n * OUT_IMG + (long long)i * OUT_W + (j4 << 2);
    float4* __restrict__ o4 = reinterpret_cast<float4*>(out) + (obase >> 2);
    const long long bs4 = BAND_STRIDE >> 2;   // band stride in float4 units

    // Streaming (evict-first) stores: output is write-once, never re-read.
    __stcs(o4,           ll);   // LL
    __stcs(o4 + bs4,     lh);   // LH
    __stcs(o4 + 2 * bs4, hl);   // HL
    __stcs(o4 + 3 * bs4, hh);   // HH
}

extern "C" void kernel_launch(void* const* d_in, const int* in_sizes, int n_in,
                              void* d_out, int out_size)
{
    const float* x = (const float*)d_in[0];   // [16,64,256,256] f32
    // d_in[1..4] are the Haar DWT matrices -- algebraically folded, unused.
    float* out = (float*)d_out;               // 4 x [16,64,128,128] f32 concat

    // total threads = 1024 * 128 * 32 = 4,194,304
    int threads = 256;
    int blocks  = (NIMG * 128 * 32) / threads;  // 16384
    dwt2d_haar_kernel<<<blocks, threads>>>(x, out);
}